// round 8
// baseline (speedup 1.0000x reference)
#include <cuda_runtime.h>
#include <cstdint>

#define NB 2
#define NS 2048
#define ND 4096
#define NH 16
#define NHD 256

#define BK 16
#define AST 20                 // smem row stride in floats (80B: conflict-free, 16B-aligned)
#define STAGE_A (128*AST*4)    // A tile bytes/stage: 10240
#define STAGE_BB (256*AST*4)   // B tile bytes/stage: 20480
#define STAGE_SZ (STAGE_A+STAGE_BB)
#define NSTAGE 4
#define SMEM_SZ (NSTAGE*STAGE_SZ)   // 122880

// ---------------- scratch (__device__ globals; no allocation) ----------------
static __device__ float g_hid  [(size_t)NB*NS*ND];     // tf32-rounded hidden
static __device__ float g_wqkvT[(size_t)3*ND*ND];      // [3D, D] rounded
static __device__ float g_woutT[(size_t)ND*ND];        // [D, D] rounded
static __device__ float g_qkv  [(size_t)NB*NS*3*ND];   // [B,S,3D] raw fp32
static __device__ float g_q    [(size_t)NB*NH*NS*NHD]; // [B,H,S,hd] rounded (roped)
static __device__ float g_k    [(size_t)NB*NH*NS*NHD]; // [B,H,S,hd] rounded (roped)
static __device__ float g_v    [(size_t)NB*NH*NS*NHD]; // [B,H,S,hd] raw
static __device__ float g_vT   [(size_t)NB*NH*NHD*NS]; // [B,H,hd,S] rounded
static __device__ float g_sc   [(size_t)NB*NH*NS*NS];  // scores / probs(rounded)
static __device__ float g_at   [(size_t)NB*NS*ND];     // [B,S,D] rounded

// ---------------- helpers ----------------
__device__ __forceinline__ unsigned f2tf(float f){
  unsigned u; asm("cvt.rna.tf32.f32 %0,%1;":"=r"(u):"f"(f)); return u;
}
__device__ __forceinline__ float f2tff(float f){ return __uint_as_float(f2tf(f)); }

__device__ __forceinline__ void mmaop(float* c, const unsigned* a, const unsigned* b){
  asm volatile(
    "mma.sync.aligned.m16n8k8.row.col.f32.tf32.tf32.f32 "
    "{%0,%1,%2,%3},{%4,%5,%6,%7},{%8,%9},{%0,%1,%2,%3};\n"
    : "+f"(c[0]),"+f"(c[1]),"+f"(c[2]),"+f"(c[3])
    : "r"(a[0]),"r"(a[1]),"r"(a[2]),"r"(a[3]),"r"(b[0]),"r"(b[1]));
}
__device__ __forceinline__ void ldsm4(unsigned addr, unsigned* r){
  asm volatile("ldmatrix.sync.aligned.m8n8.x4.shared.b16 {%0,%1,%2,%3}, [%4];"
    : "=r"(r[0]),"=r"(r[1]),"=r"(r[2]),"=r"(r[3]) : "r"(addr));
}
__device__ __forceinline__ void cpa16(unsigned dst, const float* g){
  asm volatile("cp.async.cg.shared.global [%0],[%1],16;\n"::"r"(dst),"l"(g));
}
#define CP_COMMIT() asm volatile("cp.async.commit_group;\n")
#define CP_WAIT2()  asm volatile("cp.async.wait_group 2;\n")
__device__ __forceinline__ unsigned smem_u32(const void* p){
  unsigned a; asm("{ .reg .u64 t; cvta.to.shared.u64 t, %1; cvt.u32.u64 %0, t; }":"=r"(a):"l"(p));
  return a;
}

// ============================================================================
// tf32 GEMM via mma.sync + ldmatrix: C = A[M,K] * B[N,K]^T, both K-major,
// ALL inputs pre-rounded to tf32. CTA tile 128x256, warp tile 64x64 (8 warps),
// BK=16, 4-stage cp.async, one __syncthreads per K-tile.
// causal==1: skip 2*bn>bm.  causal==2: kend=(bm+1)*128.
// C offset = (z/cdiv)*cs1 + (z%cdiv)*cs2.  round_c: tf32-round stored C.
// ============================================================================
__global__ void __launch_bounds__(256,1) gemm_tf32(
  const float* __restrict__ A, const float* __restrict__ B, float* __restrict__ C,
  int K,int lda,int ldb,int ldc,
  long long sA,long long sB,long long cs1,long long cs2,int cdiv,
  int causal,int round_c)
{
  const int bn=blockIdx.x, bm=blockIdx.y, z=blockIdx.z;
  if(causal==1 && 2*bn>bm) return;
  int kend=K;
  if(causal==2){ int ke=(bm+1)*128; if(ke<kend) kend=ke; }
  const int nk = kend>>4;            // >= 8 for every launch here

  extern __shared__ float smem[];
  const unsigned sb = smem_u32(smem);

  const int tid=threadIdx.x, warp=tid>>5, lane=tid&31;
  const int wm=warp>>2, wn=warp&3;           // 2x4 warp grid; warp tile 64x64
  const int gq=lane>>2, tg=lane&3;

  const float* Ab = A + (long long)z*sA + (long long)(bm*128)*lda;
  const float* Bb = B + (long long)z*sB + (long long)(bn*256)*ldb;

  // A staging: thread t covers row t>>1, half (t&1) (8 floats)
  const int arow = tid>>1, ahalf = tid&1;
  const float* Ag = Ab + (long long)arow*lda + ahalf*8;
  const unsigned aso = (unsigned)(arow*AST + ahalf*8)*4;
  // B staging: thread t covers row t (256 rows), 16 floats = 4 chunks
  const float* Bg = Bb + (long long)tid*ldb;
  const unsigned bso = (unsigned)(tid*AST)*4;

  // ldmatrix per-lane base offsets
  const unsigned lrow = lane & 15, lcol = (lane >> 4) << 2;
  unsigned aoff[4], boff[4];
#pragma unroll
  for(int mi=0;mi<4;mi++) aoff[mi] = ((wm*64 + mi*16 + lrow)*AST + lcol)*4;
#pragma unroll
  for(int p=0;p<4;p++)    boff[p] = ((wn*64 + p*16 + lrow)*AST + lcol)*4 + STAGE_A;

  auto stage=[&](int kt,int s){
    unsigned base = sb + s*STAGE_SZ;
    const float* ap = Ag + kt*BK;
    cpa16(base + aso,      ap);
    cpa16(base + aso + 16, ap+4);
    const float* bp = Bg + kt*BK;
    unsigned bb = base + STAGE_A + bso;
    cpa16(bb,      bp);
    cpa16(bb + 16, bp+4);
    cpa16(bb + 32, bp+8);
    cpa16(bb + 48, bp+12);
  };

  float acc[4][8][4];
#pragma unroll
  for(int i=0;i<4;i++)
#pragma unroll
    for(int j=0;j<8;j++)
#pragma unroll
      for(int l=0;l<4;l++) acc[i][j][l]=0.f;

  stage(0,0); CP_COMMIT();
  stage(1,1); CP_COMMIT();
  stage(2,2); CP_COMMIT();

  for(int kt=0; kt<nk; ++kt){
    CP_WAIT2();                       // FIFO: oldest (kt) group complete
    __syncthreads();                  // stage-kt visible; buf (kt+3)&3 free

    if(kt+3<nk) stage(kt+3,(kt+3)&3);
    CP_COMMIT();                      // uniform group accounting at tail

    const unsigned base = sb + (kt&3)*STAGE_SZ;
#pragma unroll
    for(int ks=0;ks<2;ks++){
      const unsigned kb = ks*8*4;
      unsigned a[4][4], br[4][4];
#pragma unroll
      for(int mi=0;mi<4;mi++) ldsm4(base + aoff[mi] + kb, a[mi]);
#pragma unroll
      for(int p=0;p<4;p++)    ldsm4(base + boff[p] + kb, br[p]);
      // br[p] = {b0(ni=2p), b0(ni=2p+1), b1(ni=2p), b1(ni=2p+1)}
      unsigned b[8][2];
#pragma unroll
      for(int p=0;p<4;p++){
        b[2*p  ][0]=br[p][0]; b[2*p  ][1]=br[p][2];
        b[2*p+1][0]=br[p][1]; b[2*p+1][1]=br[p][3];
      }
#pragma unroll
      for(int mi=0;mi<4;mi++)
#pragma unroll
        for(int ni=0;ni<8;ni++)
          mmaop(acc[mi][ni], a[mi], b[ni]);
    }
  }

  const long long coff = (long long)(z/cdiv)*cs1 + (long long)(z%cdiv)*cs2;
#pragma unroll
  for(int mi=0;mi<4;mi++){
    int r0 = bm*128 + wm*64 + mi*16 + gq;
#pragma unroll
    for(int ni=0;ni<8;ni++){
      int c0 = bn*256 + wn*64 + ni*8 + tg*2;
      float* p = C + coff + (long long)r0*ldc + c0;
      float2 v0 = make_float2(acc[mi][ni][0], acc[mi][ni][1]);
      float2 v1 = make_float2(acc[mi][ni][2], acc[mi][ni][3]);
      if(round_c){
        v0.x=f2tff(v0.x); v0.y=f2tff(v0.y);
        v1.x=f2tff(v1.x); v1.y=f2tff(v1.y);
      }
      *(float2*)p             = v0;
      *(float2*)(p + 8LL*ldc) = v1;
    }
  }
}

// ---------------- elementwise tf32 rounding copy ----------------
__global__ __launch_bounds__(256) void conv_round(const float* __restrict__ in, float* __restrict__ out){
  size_t i = (size_t)(blockIdx.x*256u + threadIdx.x)*4u;
  float4 v = *(const float4*)(in+i);
  v.x=f2tff(v.x); v.y=f2tff(v.y); v.z=f2tff(v.z); v.w=f2tff(v.w);
  *(float4*)(out+i)=v;
}

// ---------------- weight transpose [K,N] -> [N,K] (tf32-rounded) ----------------
__global__ __launch_bounds__(256) void transpose_w(const float* __restrict__ in, float* __restrict__ out,
                                                   int K,int N){
  __shared__ float t[32][33];
  int n0=blockIdx.x*32, k0=blockIdx.y*32;
  int tx=threadIdx.x, ty=threadIdx.y;        // 32 x 8
#pragma unroll
  for(int j=0;j<4;j++) t[ty+8*j][tx] = in[(long long)(k0+ty+8*j)*N + n0+tx];
  __syncthreads();
#pragma unroll
  for(int j=0;j<4;j++) out[(long long)(n0+ty+8*j)*K + k0+tx] = f2tff(t[tx][ty+8*j]);
}

// ---------------- batched V transpose: [z][S,hd] -> [z][hd,S] (rounded) -------
__global__ __launch_bounds__(256) void transpose_v(const float* __restrict__ in, float* __restrict__ out){
  __shared__ float t[32][33];
  int z=blockIdx.z;
  int d0=blockIdx.x*32, s0=blockIdx.y*32;
  int tx=threadIdx.x, ty=threadIdx.y;        // 32 x 8
  const float* ip = in  + (long long)z*NS*NHD;
  float*       op = out + (long long)z*NHD*NS;
#pragma unroll
  for(int j=0;j<4;j++) t[ty+8*j][tx] = ip[(long long)(s0+ty+8*j)*NHD + d0+tx];
  __syncthreads();
#pragma unroll
  for(int j=0;j<4;j++) op[(long long)(d0+ty+8*j)*NS + s0+tx] = f2tff(t[tx][ty+8*j]);
}

// ---------------- split qkv -> q,k (roped+rounded) and v (raw) ----------------
__global__ __launch_bounds__(256) void prep_rope(
  const float* __restrict__ qkv, const int* __restrict__ pos_ids,
  float* __restrict__ q, float* __restrict__ k, float* __restrict__ v)
{
  int t = blockIdx.x*blockDim.x + threadIdx.x;
  int d4 = t & 63; int r = t>>6;
  int s = r & (NS-1); r >>= 11;
  int h = r & (NH-1); r >>= 4;
  int b = r & 1; int tensor = r>>1;

  float4 x = *(const float4*)(qkv + (long long)(b*NS+s)*(3*ND) + tensor*ND + h*NHD + d4*4);

  if (tensor<2 && d4<16){
    float pos = (float)pos_ids[b*NS+s];
    int i0 = d4*2, i1 = d4*2+1;
    float inv0 = 1.0f/powf(10000.0f, (float)(2*i0)*(1.0f/64.0f));
    float inv1 = 1.0f/powf(10000.0f, (float)(2*i1)*(1.0f/64.0f));
    float f0 = pos*inv0, f1 = pos*inv1;
    float c0=cosf(f0), s0=sinf(f0), c1=cosf(f1), s1=sinf(f1);
    x = make_float4(x.x*c0 - x.y*s0, x.y*c0 + x.x*s0,
                    x.z*c1 - x.w*s1, x.w*c1 + x.z*s1);
  }
  if(tensor<2){ x.x=f2tff(x.x); x.y=f2tff(x.y); x.z=f2tff(x.z); x.w=f2tff(x.w); }
  float* dst = (tensor==0)? q : (tensor==1)? k : v;
  *(float4*)(dst + (long long)((b*NH+h)*NS+s)*NHD + d4*4) = x;
}

// ---------------- causal softmax (probs tf32-rounded; zero-fill to 128 bdry) --
__global__ __launch_bounds__(256) void softmax_causal(float* __restrict__ sc){
  const int m=blockIdx.x, z=blockIdx.y;
  float* row = sc + ((long long)z*NS + m)*NS;
  const int valid=m+1;
  const int zlim=((m>>7)+1)<<7;
  const int tid=threadIdx.x;
  const float scale=0.0625f;
  float vals[8];
  float mx=-3.0e38f;
#pragma unroll
  for(int i=0;i<8;i++){
    int j=tid+(i<<8);
    float vv=-3.0e38f;
    if(j<valid) vv=row[j]*scale;
    vals[i]=vv; mx=fmaxf(mx,vv);
  }
  __shared__ float redm[8], reds[8];
#pragma unroll
  for(int o=16;o>0;o>>=1) mx=fmaxf(mx,__shfl_xor_sync(0xffffffffu,mx,o));
  if((tid&31)==0) redm[tid>>5]=mx;
  __syncthreads();
  mx=redm[0];
#pragma unroll
  for(int i=1;i<8;i++) mx=fmaxf(mx,redm[i]);
  float sum=0.f;
#pragma unroll
  for(int i=0;i<8;i++){ float e=expf(vals[i]-mx); vals[i]=e; sum+=e; }
#pragma unroll
  for(int o=16;o>0;o>>=1) sum+=__shfl_xor_sync(0xffffffffu,sum,o);
  if((tid&31)==0) reds[tid>>5]=sum;
  __syncthreads();
  sum=0.f;
#pragma unroll
  for(int i=0;i<8;i++) sum+=reds[i];
  float inv=1.0f/sum;
#pragma unroll
  for(int i=0;i<8;i++){
    int j=tid+(i<<8);
    if(j<zlim) row[j] = (j<valid)? f2tff(vals[i]*inv) : 0.f;
  }
}

// ---------------- launch ----------------
extern "C" void kernel_launch(void* const* d_in, const int* in_sizes, int n_in,
                              void* d_out, int out_size)
{
  const int*   pos  = (const int*)d_in[0];
  const float* hid  = (const float*)d_in[1];
  const float* wqkv = (const float*)d_in[2];
  const float* wout = (const float*)d_in[3];
  float* out = (float*)d_out;

  float *hidr,*wqkvT,*woutT,*qkv,*q,*k,*v,*vT,*sc,*at;
  cudaGetSymbolAddress((void**)&hidr, g_hid);
  cudaGetSymbolAddress((void**)&wqkvT,g_wqkvT);
  cudaGetSymbolAddress((void**)&woutT,g_woutT);
  cudaGetSymbolAddress((void**)&qkv,  g_qkv);
  cudaGetSymbolAddress((void**)&q,    g_q);
  cudaGetSymbolAddress((void**)&k,    g_k);
  cudaGetSymbolAddress((void**)&v,    g_v);
  cudaGetSymbolAddress((void**)&vT,   g_vT);
  cudaGetSymbolAddress((void**)&sc,   g_sc);
  cudaGetSymbolAddress((void**)&at,   g_at);

  cudaFuncSetAttribute(gemm_tf32, cudaFuncAttributeMaxDynamicSharedMemorySize, SMEM_SZ);

  // 0) round / transpose inputs
  conv_round<<<((size_t)NB*NS*ND)/1024, 256>>>(hid, hidr);
  transpose_w<<<dim3((3*ND)/32, ND/32), dim3(32,8)>>>(wqkv, wqkvT, ND, 3*ND);
  transpose_w<<<dim3(ND/32, ND/32),     dim3(32,8)>>>(wout, woutT, ND, ND);

  // 1) qkv = hid @ WqkvT^T   (M=4096, N=12288, K=4096)
  gemm_tf32<<<dim3((3*ND)/256,(NB*NS)/128,1),256,SMEM_SZ>>>(
      hidr,wqkvT,qkv, ND, ND,ND,3*ND, 0,0, 0,0,1, 0,0);

  // 2) split + rope
  prep_rope<<<(3*NB*NH*NS*64)/256,256>>>(qkv,pos,q,k,v);
  transpose_v<<<dim3(NHD/32,NS/32,NB*NH), dim3(32,8)>>>(v, vT);

  // 3) scores = Q @ K^T (causal block-skip)
  gemm_tf32<<<dim3(NS/256,NS/128,NB*NH),256,SMEM_SZ>>>(
      q,k,sc, NHD, NHD,NHD,NS,
      (long long)NS*NHD,(long long)NS*NHD,
      (long long)NS*NS,0,1, 1,0);

  // 4) softmax (rounds probs)
  softmax_causal<<<dim3(NS,NB*NH),256>>>(sc);

  // 5) attn = P @ V (causal K-limit), write [B,S,D], rounded
  gemm_tf32<<<dim3(NHD/256,NS/128,NB*NH),256,SMEM_SZ>>>(
      sc,vT,at, NS, NS,NS,ND,
      (long long)NS*NS,(long long)NHD*NS,
      (long long)NS*ND,(long long)NHD,NH, 2,1);

  // 6) out = attn @ WoutT^T
  gemm_tf32<<<dim3(ND/256,(NB*NS)/128,1),256,SMEM_SZ>>>(
      at,woutT,out, ND, ND,ND,ND, 0,0, 0,0,1, 0,0);
}

// round 9
// speedup vs baseline: 1.6580x; 1.6580x over previous
#include <cuda_runtime.h>
#include <cstdint>

#define NB 2
#define NS 2048
#define ND 4096
#define NH 16
#define NHD 256

#define BK 32                    // K floats per tile = 128B SW128 row
#define STAGE_M 16384            // one 128-row x 128B matrix
#define STAGE_SZ (2*STAGE_M)     // A + B = 32KB
#define NSTAGE 3
#define SMEM_SZ (NSTAGE*STAGE_SZ)   // 98304 -> 2 CTAs/SM

// ---------------- scratch (__device__ globals; no allocation) ----------------
static __device__ float g_hid  [(size_t)NB*NS*ND];     // tf32-rounded hidden
static __device__ float g_wqkvT[(size_t)3*ND*ND];      // [3D, D] rounded
static __device__ float g_woutT[(size_t)ND*ND];        // [D, D] rounded
static __device__ float g_qkv  [(size_t)NB*NS*3*ND];   // [B,S,3D] raw fp32
static __device__ float g_q    [(size_t)NB*NH*NS*NHD]; // [B,H,S,hd] rounded (roped)
static __device__ float g_k    [(size_t)NB*NH*NS*NHD]; // [B,H,S,hd] rounded (roped)
static __device__ float g_v    [(size_t)NB*NH*NS*NHD]; // [B,H,S,hd] raw
static __device__ float g_vT   [(size_t)NB*NH*NHD*NS]; // [B,H,hd,S] rounded
static __device__ float g_sc   [(size_t)NB*NH*NS*NS];  // scores / probs(rounded)
static __device__ float g_at   [(size_t)NB*NS*ND];     // [B,S,D] rounded

// ---------------- helpers ----------------
__device__ __forceinline__ unsigned f2tf(float f){
  unsigned u; asm("cvt.rna.tf32.f32 %0,%1;":"=r"(u):"f"(f)); return u;
}
__device__ __forceinline__ float f2tff(float f){ return __uint_as_float(f2tf(f)); }

__device__ __forceinline__ void mmaop(float* c, const unsigned* a, const unsigned* b){
  asm volatile(
    "mma.sync.aligned.m16n8k8.row.col.f32.tf32.tf32.f32 "
    "{%0,%1,%2,%3},{%4,%5,%6,%7},{%8,%9},{%0,%1,%2,%3};\n"
    : "+f"(c[0]),"+f"(c[1]),"+f"(c[2]),"+f"(c[3])
    : "r"(a[0]),"r"(a[1]),"r"(a[2]),"r"(a[3]),"r"(b[0]),"r"(b[1]));
}
__device__ __forceinline__ void ldsm4(unsigned addr, unsigned* r){
  asm volatile("ldmatrix.sync.aligned.m8n8.x4.shared.b16 {%0,%1,%2,%3}, [%4];"
    : "=r"(r[0]),"=r"(r[1]),"=r"(r[2]),"=r"(r[3]) : "r"(addr));
}
__device__ __forceinline__ void cpa16(unsigned dst, const float* g){
  asm volatile("cp.async.cg.shared.global [%0],[%1],16;\n"::"r"(dst),"l"(g));
}
#define CP_COMMIT() asm volatile("cp.async.commit_group;\n")
#define CP_WAIT1()  asm volatile("cp.async.wait_group 1;\n")
__device__ __forceinline__ unsigned smem_u32(const void* p){
  unsigned a; asm("{ .reg .u64 t; cvta.to.shared.u64 t, %1; cvt.u32.u64 %0, t; }":"=r"(a):"l"(p));
  return a;
}

// ============================================================================
// tf32 GEMM via mma.sync + ldmatrix: C = A[M,K] * B[N,K]^T, both K-major,
// ALL inputs pre-rounded to tf32. CTA tile 128x128 (8 warps, 64x32 warp tile),
// BK=32 with SW128 swizzle, 3-stage cp.async, one __syncthreads per 32-K.
// causal==1: skip bn>bm.  causal==2: kend=(bm+1)*128.
// C offset = (z/cdiv)*cs1 + (z%cdiv)*cs2.  round_c: tf32-round stored C.
// ============================================================================
__global__ void __launch_bounds__(256,2) gemm_tf32(
  const float* __restrict__ A, const float* __restrict__ B, float* __restrict__ C,
  int K,int lda,int ldb,int ldc,
  long long sA,long long sB,long long cs1,long long cs2,int cdiv,
  int causal,int round_c)
{
  const int bn=blockIdx.x, bm=blockIdx.y, z=blockIdx.z;
  if(causal==1 && bn>bm) return;
  int kend=K;
  if(causal==2){ int ke=(bm+1)*128; if(ke<kend) kend=ke; }
  const int nk = kend>>5;            // >= 4 for every launch here

  extern __shared__ float smem[];
  const unsigned sb = smem_u32(smem);

  const int tid=threadIdx.x, warp=tid>>5, lane=tid&31;
  const int wm=warp>>2, wn=warp&3;           // 2x4 warp grid; warp tile 64x32
  const int gq=lane>>2, tg=lane&3;

  const float* Ab = A + (long long)z*sA + (long long)(bm*128)*lda;
  const float* Bb = B + (long long)z*sB + (long long)(bn*128)*ldb;

  // staging: 1024 16B-chunks per matrix; thread t covers chunks {t, t+256, t+512, t+768}
  const float* gA[4]; const float* gB[4]; unsigned sAo[4], sBo[4];
#pragma unroll
  for(int i=0;i<4;i++){
    int q=i*256+tid, row=q>>3, c=q&7;
    unsigned sw = (unsigned)(row*128 + ((c ^ (row&7))<<4));   // SW128
    sAo[i]=sw; sBo[i]=sw;
    gA[i]=Ab + (long long)row*lda + c*4;
    gB[i]=Bb + (long long)row*ldb + c*4;
  }

  auto stage=[&](int kt,int s){
    unsigned base = sb + s*STAGE_SZ;
#pragma unroll
    for(int i=0;i<4;i++) cpa16(base + sAo[i],           gA[i] + kt*BK);
#pragma unroll
    for(int i=0;i<4;i++) cpa16(base + STAGE_M + sBo[i], gB[i] + kt*BK);
  };

  // ldmatrix per-lane row constants (row byte-base and swizzle key)
  const int lrow = lane & 15;
  const unsigned klane = lane >> 4;          // 16B half within 32B k-chunk
  unsigned ar128[4], ar7[4], br128[2], br7[2];
#pragma unroll
  for(int mi=0;mi<4;mi++){
    int r = wm*64 + mi*16 + lrow;
    ar128[mi] = r*128; ar7[mi] = r&7;
  }
#pragma unroll
  for(int p=0;p<2;p++){
    int r = wn*32 + p*16 + lrow;
    br128[p] = r*128 + STAGE_M; br7[p] = r&7;
  }

  float acc[4][4][4];
#pragma unroll
  for(int i=0;i<4;i++)
#pragma unroll
    for(int j=0;j<4;j++)
#pragma unroll
      for(int l=0;l<4;l++) acc[i][j][l]=0.f;

  stage(0,0); CP_COMMIT();
  stage(1,1); CP_COMMIT();

  for(int kt=0; kt<nk; ++kt){
    CP_WAIT1();                       // FIFO: oldest (kt) group complete
    __syncthreads();                  // stage-kt visible; buf (kt+2)%3 free

    if(kt+2<nk) stage(kt+2,(kt+2)%3);
    CP_COMMIT();                      // uniform group accounting at tail

    const unsigned base = sb + (unsigned)(kt%3)*STAGE_SZ;
#pragma unroll
    for(int ks=0;ks<4;ks++){
      const unsigned ck = ks*2 + klane;       // 16B chunk index 0..7
      unsigned a[4][4], br[2][4];
#pragma unroll
      for(int mi=0;mi<4;mi++)
        ldsm4(base + ar128[mi] + (((ck ^ ar7[mi]))<<4), a[mi]);
#pragma unroll
      for(int p=0;p<2;p++)
        ldsm4(base + br128[p] + (((ck ^ br7[p]))<<4), br[p]);
      // br[p] = {b0(ni=2p), b0(ni=2p+1), b1(ni=2p), b1(ni=2p+1)}
      unsigned b[4][2];
#pragma unroll
      for(int p=0;p<2;p++){
        b[2*p  ][0]=br[p][0]; b[2*p  ][1]=br[p][2];
        b[2*p+1][0]=br[p][1]; b[2*p+1][1]=br[p][3];
      }
#pragma unroll
      for(int mi=0;mi<4;mi++)
#pragma unroll
        for(int ni=0;ni<4;ni++)
          mmaop(acc[mi][ni], a[mi], b[ni]);
    }
  }

  const long long coff = (long long)(z/cdiv)*cs1 + (long long)(z%cdiv)*cs2;
#pragma unroll
  for(int mi=0;mi<4;mi++){
    int r0 = bm*128 + wm*64 + mi*16 + gq;
#pragma unroll
    for(int ni=0;ni<4;ni++){
      int c0 = bn*128 + wn*32 + ni*8 + tg*2;
      float* p = C + coff + (long long)r0*ldc + c0;
      float2 v0 = make_float2(acc[mi][ni][0], acc[mi][ni][1]);
      float2 v1 = make_float2(acc[mi][ni][2], acc[mi][ni][3]);
      if(round_c){
        v0.x=f2tff(v0.x); v0.y=f2tff(v0.y);
        v1.x=f2tff(v1.x); v1.y=f2tff(v1.y);
      }
      *(float2*)p             = v0;
      *(float2*)(p + 8LL*ldc) = v1;
    }
  }
}

// ---------------- elementwise tf32 rounding copy ----------------
__global__ __launch_bounds__(256) void conv_round(const float* __restrict__ in, float* __restrict__ out){
  size_t i = (size_t)(blockIdx.x*256u + threadIdx.x)*4u;
  float4 v = *(const float4*)(in+i);
  v.x=f2tff(v.x); v.y=f2tff(v.y); v.z=f2tff(v.z); v.w=f2tff(v.w);
  *(float4*)(out+i)=v;
}

// ---------------- weight transpose [K,N] -> [N,K] (tf32-rounded) ----------------
__global__ __launch_bounds__(256) void transpose_w(const float* __restrict__ in, float* __restrict__ out,
                                                   int K,int N){
  __shared__ float t[32][33];
  int n0=blockIdx.x*32, k0=blockIdx.y*32;
  int tx=threadIdx.x, ty=threadIdx.y;        // 32 x 8
#pragma unroll
  for(int j=0;j<4;j++) t[ty+8*j][tx] = in[(long long)(k0+ty+8*j)*N + n0+tx];
  __syncthreads();
#pragma unroll
  for(int j=0;j<4;j++) out[(long long)(n0+ty+8*j)*K + k0+tx] = f2tff(t[tx][ty+8*j]);
}

// ---------------- batched V transpose: [z][S,hd] -> [z][hd,S] (rounded) -------
__global__ __launch_bounds__(256) void transpose_v(const float* __restrict__ in, float* __restrict__ out){
  __shared__ float t[32][33];
  int z=blockIdx.z;
  int d0=blockIdx.x*32, s0=blockIdx.y*32;
  int tx=threadIdx.x, ty=threadIdx.y;        // 32 x 8
  const float* ip = in  + (long long)z*NS*NHD;
  float*       op = out + (long long)z*NHD*NS;
#pragma unroll
  for(int j=0;j<4;j++) t[ty+8*j][tx] = ip[(long long)(s0+ty+8*j)*NHD + d0+tx];
  __syncthreads();
#pragma unroll
  for(int j=0;j<4;j++) op[(long long)(d0+ty+8*j)*NS + s0+tx] = f2tff(t[tx][ty+8*j]);
}

// ---------------- split qkv -> q,k (roped+rounded) and v (raw) ----------------
__global__ __launch_bounds__(256) void prep_rope(
  const float* __restrict__ qkv, const int* __restrict__ pos_ids,
  float* __restrict__ q, float* __restrict__ k, float* __restrict__ v)
{
  int t = blockIdx.x*blockDim.x + threadIdx.x;
  int d4 = t & 63; int r = t>>6;
  int s = r & (NS-1); r >>= 11;
  int h = r & (NH-1); r >>= 4;
  int b = r & 1; int tensor = r>>1;

  float4 x = *(const float4*)(qkv + (long long)(b*NS+s)*(3*ND) + tensor*ND + h*NHD + d4*4);

  if (tensor<2 && d4<16){
    float pos = (float)pos_ids[b*NS+s];
    int i0 = d4*2, i1 = d4*2+1;
    float inv0 = 1.0f/powf(10000.0f, (float)(2*i0)*(1.0f/64.0f));
    float inv1 = 1.0f/powf(10000.0f, (float)(2*i1)*(1.0f/64.0f));
    float f0 = pos*inv0, f1 = pos*inv1;
    float c0=cosf(f0), s0=sinf(f0), c1=cosf(f1), s1=sinf(f1);
    x = make_float4(x.x*c0 - x.y*s0, x.y*c0 + x.x*s0,
                    x.z*c1 - x.w*s1, x.w*c1 + x.z*s1);
  }
  if(tensor<2){ x.x=f2tff(x.x); x.y=f2tff(x.y); x.z=f2tff(x.z); x.w=f2tff(x.w); }
  float* dst = (tensor==0)? q : (tensor==1)? k : v;
  *(float4*)(dst + (long long)((b*NH+h)*NS+s)*NHD + d4*4) = x;
}

// ---------------- causal softmax (probs tf32-rounded; zero-fill to 128 bdry) --
__global__ __launch_bounds__(256) void softmax_causal(float* __restrict__ sc){
  const int m=blockIdx.x, z=blockIdx.y;
  float* row = sc + ((long long)z*NS + m)*NS;
  const int valid=m+1;
  const int zlim=((m>>7)+1)<<7;
  const int tid=threadIdx.x;
  const float scale=0.0625f;
  float vals[8];
  float mx=-3.0e38f;
#pragma unroll
  for(int i=0;i<8;i++){
    int j=tid+(i<<8);
    float vv=-3.0e38f;
    if(j<valid) vv=row[j]*scale;
    vals[i]=vv; mx=fmaxf(mx,vv);
  }
  __shared__ float redm[8], reds[8];
#pragma unroll
  for(int o=16;o>0;o>>=1) mx=fmaxf(mx,__shfl_xor_sync(0xffffffffu,mx,o));
  if((tid&31)==0) redm[tid>>5]=mx;
  __syncthreads();
  mx=redm[0];
#pragma unroll
  for(int i=1;i<8;i++) mx=fmaxf(mx,redm[i]);
  float sum=0.f;
#pragma unroll
  for(int i=0;i<8;i++){ float e=expf(vals[i]-mx); vals[i]=e; sum+=e; }
#pragma unroll
  for(int o=16;o>0;o>>=1) sum+=__shfl_xor_sync(0xffffffffu,sum,o);
  if((tid&31)==0) reds[tid>>5]=sum;
  __syncthreads();
  sum=0.f;
#pragma unroll
  for(int i=0;i<8;i++) sum+=reds[i];
  float inv=1.0f/sum;
#pragma unroll
  for(int i=0;i<8;i++){
    int j=tid+(i<<8);
    if(j<zlim) row[j] = (j<valid)? f2tff(vals[i]*inv) : 0.f;
  }
}

// ---------------- launch ----------------
extern "C" void kernel_launch(void* const* d_in, const int* in_sizes, int n_in,
                              void* d_out, int out_size)
{
  const int*   pos  = (const int*)d_in[0];
  const float* hid  = (const float*)d_in[1];
  const float* wqkv = (const float*)d_in[2];
  const float* wout = (const float*)d_in[3];
  float* out = (float*)d_out;

  float *hidr,*wqkvT,*woutT,*qkv,*q,*k,*v,*vT,*sc,*at;
  cudaGetSymbolAddress((void**)&hidr, g_hid);
  cudaGetSymbolAddress((void**)&wqkvT,g_wqkvT);
  cudaGetSymbolAddress((void**)&woutT,g_woutT);
  cudaGetSymbolAddress((void**)&qkv,  g_qkv);
  cudaGetSymbolAddress((void**)&q,    g_q);
  cudaGetSymbolAddress((void**)&k,    g_k);
  cudaGetSymbolAddress((void**)&v,    g_v);
  cudaGetSymbolAddress((void**)&vT,   g_vT);
  cudaGetSymbolAddress((void**)&sc,   g_sc);
  cudaGetSymbolAddress((void**)&at,   g_at);

  cudaFuncSetAttribute(gemm_tf32, cudaFuncAttributeMaxDynamicSharedMemorySize, SMEM_SZ);

  // 0) round / transpose inputs
  conv_round<<<((size_t)NB*NS*ND)/1024, 256>>>(hid, hidr);
  transpose_w<<<dim3((3*ND)/32, ND/32), dim3(32,8)>>>(wqkv, wqkvT, ND, 3*ND);
  transpose_w<<<dim3(ND/32, ND/32),     dim3(32,8)>>>(wout, woutT, ND, ND);

  // 1) qkv = hid @ WqkvT^T   (M=4096, N=12288, K=4096)
  gemm_tf32<<<dim3((3*ND)/128,(NB*NS)/128,1),256,SMEM_SZ>>>(
      hidr,wqkvT,qkv, ND, ND,ND,3*ND, 0,0, 0,0,1, 0,0);

  // 2) split + rope
  prep_rope<<<(3*NB*NH*NS*64)/256,256>>>(qkv,pos,q,k,v);
  transpose_v<<<dim3(NHD/32,NS/32,NB*NH), dim3(32,8)>>>(v, vT);

  // 3) scores = Q @ K^T (causal block-skip)
  gemm_tf32<<<dim3(NS/128,NS/128,NB*NH),256,SMEM_SZ>>>(
      q,k,sc, NHD, NHD,NHD,NS,
      (long long)NS*NHD,(long long)NS*NHD,
      (long long)NS*NS,0,1, 1,0);

  // 4) softmax (rounds probs)
  softmax_causal<<<dim3(NS,NB*NH),256>>>(sc);

  // 5) attn = P @ V (causal K-limit), write [B,S,D], rounded
  gemm_tf32<<<dim3(NHD/128,NS/128,NB*NH),256,SMEM_SZ>>>(
      sc,vT,at, NS, NS,NS,ND,
      (long long)NS*NS,(long long)NHD*NS,
      (long long)NS*ND,(long long)NHD,NH, 2,1);

  // 6) out = attn @ WoutT^T
  gemm_tf32<<<dim3(ND/128,(NB*NS)/128,1),256,SMEM_SZ>>>(
      at,woutT,out, ND, ND,ND,ND, 0,0, 0,0,1, 0,0);
}

// round 10
// speedup vs baseline: 2.9847x; 1.8002x over previous
#include <cuda_runtime.h>
#include <cuda_fp16.h>
#include <cstdint>

#define NB 2
#define NS 2048
#define ND 4096
#define NH 16
#define NHD 256

#define BK 64                    // K halfs per tile = 128B SW128 row
#define STAGE_M 16384            // one 128-row x 128B matrix
#define STAGE_SZ (2*STAGE_M)     // A + B = 32KB
#define NSTAGE 3
#define SMEM_SZ (NSTAGE*STAGE_SZ)   // 98304 -> 2 CTAs/SM

// ---------------- scratch (__device__ globals; no allocation) ----------------
static __device__ __half g_hid  [(size_t)NB*NS*ND];     // fp16 hidden
static __device__ __half g_wqkvT[(size_t)3*ND*ND];      // [3D, D] fp16
static __device__ __half g_woutT[(size_t)ND*ND];        // [D, D] fp16
static __device__ __half g_qkv  [(size_t)NB*NS*3*ND];   // [B,S,3D] fp16
static __device__ __half g_q    [(size_t)NB*NH*NS*NHD]; // [B,H,S,hd] fp16 (roped)
static __device__ __half g_k    [(size_t)NB*NH*NS*NHD]; // [B,H,S,hd] fp16 (roped)
static __device__ __half g_v    [(size_t)NB*NH*NS*NHD]; // [B,H,S,hd] fp16
static __device__ __half g_vT   [(size_t)NB*NH*NHD*NS]; // [B,H,hd,S] fp16
static __device__ float  g_sc   [(size_t)NB*NH*NS*NS];  // scores fp32
static __device__ __half g_p    [(size_t)NB*NH*NS*NS];  // probs fp16
static __device__ __half g_at   [(size_t)NB*NS*ND];     // [B,S,D] fp16

// ---------------- helpers ----------------
__device__ __forceinline__ void mmaop(float* c, const unsigned* a, const unsigned* b){
  asm volatile(
    "mma.sync.aligned.m16n8k16.row.col.f32.f16.f16.f32 "
    "{%0,%1,%2,%3},{%4,%5,%6,%7},{%8,%9},{%0,%1,%2,%3};\n"
    : "+f"(c[0]),"+f"(c[1]),"+f"(c[2]),"+f"(c[3])
    : "r"(a[0]),"r"(a[1]),"r"(a[2]),"r"(a[3]),"r"(b[0]),"r"(b[1]));
}
__device__ __forceinline__ void ldsm4(unsigned addr, unsigned* r){
  asm volatile("ldmatrix.sync.aligned.m8n8.x4.shared.b16 {%0,%1,%2,%3}, [%4];"
    : "=r"(r[0]),"=r"(r[1]),"=r"(r[2]),"=r"(r[3]) : "r"(addr));
}
__device__ __forceinline__ void cpa16(unsigned dst, const void* g){
  asm volatile("cp.async.cg.shared.global [%0],[%1],16;\n"::"r"(dst),"l"(g));
}
#define CP_COMMIT() asm volatile("cp.async.commit_group;\n")
#define CP_WAIT1()  asm volatile("cp.async.wait_group 1;\n")
__device__ __forceinline__ unsigned smem_u32(const void* p){
  unsigned a; asm("{ .reg .u64 t; cvta.to.shared.u64 t, %1; cvt.u32.u64 %0, t; }":"=r"(a):"l"(p));
  return a;
}
__device__ __forceinline__ void st2(float* p, float x, float y){
  *(float2*)p = make_float2(x,y);
}
__device__ __forceinline__ void st2(__half* p, float x, float y){
  *(__half2*)p = __floats2half2_rn(x,y);
}

// ============================================================================
// fp16 GEMM via mma.sync(m16n8k16) + ldmatrix: C = A[M,K] * B[N,K]^T, K-major
// fp16 inputs, fp32 accumulate. CTA tile 128x128 (8 warps, 64x32 warp tile),
// BK=64 halfs (128B SW128 rows), 3-stage cp.async, one __syncthreads per tile.
// causal==1: skip bn>bm.  causal==2: kend=(bm+1)*128.
// C offset = (z/cdiv)*cs1 + (z%cdiv)*cs2.  CT = float or __half.
// ============================================================================
template<typename CT>
__global__ void __launch_bounds__(256,2) gemm_fp16(
  const __half* __restrict__ A, const __half* __restrict__ B, CT* __restrict__ C,
  int K,int lda,int ldb,int ldc,
  long long sA,long long sB,long long cs1,long long cs2,int cdiv,
  int causal)
{
  const int bn=blockIdx.x, bm=blockIdx.y, z=blockIdx.z;
  if(causal==1 && bn>bm) return;
  int kend=K;
  if(causal==2){ int ke=(bm+1)*128; if(ke<kend) kend=ke; }
  const int nk = kend>>6;            // >= 2 for every launch here

  extern __shared__ float smem[];
  const unsigned sb = smem_u32(smem);

  const int tid=threadIdx.x, warp=tid>>5, lane=tid&31;
  const int wm=warp>>2, wn=warp&3;           // 2x4 warp grid; warp tile 64x32
  const int gq=lane>>2, tg=lane&3;

  const __half* Ab = A + (long long)z*sA + (long long)(bm*128)*lda;
  const __half* Bb = B + (long long)z*sB + (long long)(bn*128)*ldb;

  // staging: 1024 16B-chunks per matrix; thread t covers chunks {t, t+256, t+512, t+768}
  const __half* gA[4]; const __half* gB[4]; unsigned sAo[4];
#pragma unroll
  for(int i=0;i<4;i++){
    int q=i*256+tid, row=q>>3, c=q&7;
    sAo[i] = (unsigned)(row*128 + ((c ^ (row&7))<<4));   // SW128
    gA[i]=Ab + (long long)row*lda + c*8;
    gB[i]=Bb + (long long)row*ldb + c*8;
  }

  auto stage=[&](int kt,int s){
    unsigned base = sb + s*STAGE_SZ;
#pragma unroll
    for(int i=0;i<4;i++) cpa16(base + sAo[i],           gA[i] + kt*BK);
#pragma unroll
    for(int i=0;i<4;i++) cpa16(base + STAGE_M + sAo[i], gB[i] + kt*BK);
  };

  // ldmatrix per-lane row constants (row byte-base and swizzle key)
  const int lrow = lane & 15;
  const unsigned klane = lane >> 4;          // 16B half within 32B k16-chunk
  unsigned ar128[4], ar7[4], br128[2], br7[2];
#pragma unroll
  for(int mi=0;mi<4;mi++){
    int r = wm*64 + mi*16 + lrow;
    ar128[mi] = r*128; ar7[mi] = r&7;
  }
#pragma unroll
  for(int p=0;p<2;p++){
    int r = wn*32 + p*16 + lrow;
    br128[p] = r*128 + STAGE_M; br7[p] = r&7;
  }

  float acc[4][4][4];
#pragma unroll
  for(int i=0;i<4;i++)
#pragma unroll
    for(int j=0;j<4;j++)
#pragma unroll
      for(int l=0;l<4;l++) acc[i][j][l]=0.f;

  stage(0,0); CP_COMMIT();
  stage(1,1); CP_COMMIT();

  for(int kt=0; kt<nk; ++kt){
    CP_WAIT1();                       // FIFO: oldest (kt) group complete
    __syncthreads();                  // stage-kt visible; buf (kt+2)%3 free

    if(kt+2<nk) stage(kt+2,(kt+2)%3);
    CP_COMMIT();                      // uniform group accounting at tail

    const unsigned base = sb + (unsigned)(kt%3)*STAGE_SZ;
#pragma unroll
    for(int ks=0;ks<4;ks++){          // 4 x k16 per 64-K tile
      const unsigned ck = ks*2 + klane;       // 16B chunk index 0..7
      unsigned a[4][4], br[2][4];
#pragma unroll
      for(int mi=0;mi<4;mi++)
        ldsm4(base + ar128[mi] + (((ck ^ ar7[mi]))<<4), a[mi]);
#pragma unroll
      for(int p=0;p<2;p++)
        ldsm4(base + br128[p] + (((ck ^ br7[p]))<<4), br[p]);
      // br[p] regs: {b0(n-block 2p), b0(2p+1), b1(2p), b1(2p+1)}
      unsigned b[4][2];
#pragma unroll
      for(int p=0;p<2;p++){
        b[2*p  ][0]=br[p][0]; b[2*p  ][1]=br[p][2];
        b[2*p+1][0]=br[p][1]; b[2*p+1][1]=br[p][3];
      }
#pragma unroll
      for(int mi=0;mi<4;mi++)
#pragma unroll
        for(int ni=0;ni<4;ni++)
          mmaop(acc[mi][ni], a[mi], b[ni]);
    }
  }

  const long long coff = (long long)(z/cdiv)*cs1 + (long long)(z%cdiv)*cs2;
#pragma unroll
  for(int mi=0;mi<4;mi++){
    int r0 = bm*128 + wm*64 + mi*16 + gq;
#pragma unroll
    for(int ni=0;ni<4;ni++){
      int c0 = bn*128 + wn*32 + ni*8 + tg*2;
      CT* p = C + coff + (long long)r0*ldc + c0;
      st2(p,             acc[mi][ni][0], acc[mi][ni][1]);
      st2(p + 8LL*ldc,   acc[mi][ni][2], acc[mi][ni][3]);
    }
  }
}

// ---------------- fp32 -> fp16 copy ----------------
__global__ __launch_bounds__(256) void conv_half(const float* __restrict__ in, __half* __restrict__ out){
  size_t i = (size_t)(blockIdx.x*256u + threadIdx.x)*4u;
  float4 v = *(const float4*)(in+i);
  *(__half2*)(out+i)   = __floats2half2_rn(v.x,v.y);
  *(__half2*)(out+i+2) = __floats2half2_rn(v.z,v.w);
}

// ---------------- weight transpose [K,N] fp32 -> [N,K] fp16 ----------------
__global__ __launch_bounds__(256) void transpose_w(const float* __restrict__ in, __half* __restrict__ out,
                                                   int K,int N){
  __shared__ float t[32][33];
  int n0=blockIdx.x*32, k0=blockIdx.y*32;
  int tx=threadIdx.x, ty=threadIdx.y;        // 32 x 8
#pragma unroll
  for(int j=0;j<4;j++) t[ty+8*j][tx] = in[(long long)(k0+ty+8*j)*N + n0+tx];
  __syncthreads();
#pragma unroll
  for(int j=0;j<4;j++) out[(long long)(n0+ty+8*j)*K + k0+tx] = __float2half_rn(t[tx][ty+8*j]);
}

// ---------------- batched V transpose: [z][S,hd] -> [z][hd,S] fp16 -------
__global__ __launch_bounds__(256) void transpose_v(const __half* __restrict__ in, __half* __restrict__ out){
  __shared__ float t[32][33];
  int z=blockIdx.z;
  int d0=blockIdx.x*32, s0=blockIdx.y*32;
  int tx=threadIdx.x, ty=threadIdx.y;        // 32 x 8
  const __half* ip = in  + (long long)z*NS*NHD;
  __half*       op = out + (long long)z*NHD*NS;
#pragma unroll
  for(int j=0;j<4;j++) t[ty+8*j][tx] = __half2float(ip[(long long)(s0+ty+8*j)*NHD + d0+tx]);
  __syncthreads();
#pragma unroll
  for(int j=0;j<4;j++) op[(long long)(d0+ty+8*j)*NS + s0+tx] = __float2half_rn(t[tx][ty+8*j]);
}

// ---------------- split qkv -> q,k (roped) and v, fp16 ----------------
__global__ __launch_bounds__(256) void prep_rope(
  const __half* __restrict__ qkv, const int* __restrict__ pos_ids,
  __half* __restrict__ q, __half* __restrict__ k, __half* __restrict__ v)
{
  int t = blockIdx.x*blockDim.x + threadIdx.x;
  int d4 = t & 63; int r = t>>6;
  int s = r & (NS-1); r >>= 11;
  int h = r & (NH-1); r >>= 4;
  int b = r & 1; int tensor = r>>1;

  const __half* src = qkv + (long long)(b*NS+s)*(3*ND) + tensor*ND + h*NHD + d4*4;
  float2 x01 = __half22float2(*(const __half2*)src);
  float2 x23 = __half22float2(*(const __half2*)(src+2));
  float xx=x01.x, xy=x01.y, xz=x23.x, xw=x23.y;

  if (tensor<2 && d4<16){
    float pos = (float)pos_ids[b*NS+s];
    int i0 = d4*2, i1 = d4*2+1;
    float inv0 = 1.0f/powf(10000.0f, (float)(2*i0)*(1.0f/64.0f));
    float inv1 = 1.0f/powf(10000.0f, (float)(2*i1)*(1.0f/64.0f));
    float f0 = pos*inv0, f1 = pos*inv1;
    float c0=cosf(f0), s0=sinf(f0), c1=cosf(f1), s1=sinf(f1);
    float nx = xx*c0 - xy*s0, ny = xy*c0 + xx*s0;
    float nz = xz*c1 - xw*s1, nw = xw*c1 + xz*s1;
    xx=nx; xy=ny; xz=nz; xw=nw;
  }
  __half* dst = ((tensor==0)? q : (tensor==1)? k : v)
              + (long long)((b*NH+h)*NS+s)*NHD + d4*4;
  *(__half2*)dst     = __floats2half2_rn(xx,xy);
  *(__half2*)(dst+2) = __floats2half2_rn(xz,xw);
}

// -------- causal softmax: fp32 scores -> fp16 probs (zero-fill to 128 bdry) --
__global__ __launch_bounds__(256) void softmax_causal(const float* __restrict__ sc,
                                                      __half* __restrict__ pr){
  const int m=blockIdx.x, z=blockIdx.y;
  const float* row = sc + ((long long)z*NS + m)*NS;
  __half* rowp     = pr + ((long long)z*NS + m)*NS;
  const int valid=m+1;
  const int zlim=((m>>7)+1)<<7;
  const int tid=threadIdx.x;
  const float scale=0.0625f;
  float vals[8];
  float mx=-3.0e38f;
#pragma unroll
  for(int i=0;i<8;i++){
    int j=tid+(i<<8);
    float vv=-3.0e38f;
    if(j<valid) vv=row[j]*scale;
    vals[i]=vv; mx=fmaxf(mx,vv);
  }
  __shared__ float redm[8], reds[8];
#pragma unroll
  for(int o=16;o>0;o>>=1) mx=fmaxf(mx,__shfl_xor_sync(0xffffffffu,mx,o));
  if((tid&31)==0) redm[tid>>5]=mx;
  __syncthreads();
  mx=redm[0];
#pragma unroll
  for(int i=1;i<8;i++) mx=fmaxf(mx,redm[i]);
  float sum=0.f;
#pragma unroll
  for(int i=0;i<8;i++){ float e=expf(vals[i]-mx); vals[i]=e; sum+=e; }
#pragma unroll
  for(int o=16;o>0;o>>=1) sum+=__shfl_xor_sync(0xffffffffu,sum,o);
  if((tid&31)==0) reds[tid>>5]=sum;
  __syncthreads();
  sum=0.f;
#pragma unroll
  for(int i=0;i<8;i++) sum+=reds[i];
  float inv=1.0f/sum;
#pragma unroll
  for(int i=0;i<8;i++){
    int j=tid+(i<<8);
    if(j<zlim) rowp[j] = __float2half_rn((j<valid)? vals[i]*inv : 0.f);
  }
}

// ---------------- launch ----------------
extern "C" void kernel_launch(void* const* d_in, const int* in_sizes, int n_in,
                              void* d_out, int out_size)
{
  const int*   pos  = (const int*)d_in[0];
  const float* hid  = (const float*)d_in[1];
  const float* wqkv = (const float*)d_in[2];
  const float* wout = (const float*)d_in[3];
  float* out = (float*)d_out;

  __half *hidh,*wqkvT,*woutT,*qkv,*q,*k,*v,*vT,*pr,*at;
  float *sc;
  cudaGetSymbolAddress((void**)&hidh, g_hid);
  cudaGetSymbolAddress((void**)&wqkvT,g_wqkvT);
  cudaGetSymbolAddress((void**)&woutT,g_woutT);
  cudaGetSymbolAddress((void**)&qkv,  g_qkv);
  cudaGetSymbolAddress((void**)&q,    g_q);
  cudaGetSymbolAddress((void**)&k,    g_k);
  cudaGetSymbolAddress((void**)&v,    g_v);
  cudaGetSymbolAddress((void**)&vT,   g_vT);
  cudaGetSymbolAddress((void**)&sc,   g_sc);
  cudaGetSymbolAddress((void**)&pr,   g_p);
  cudaGetSymbolAddress((void**)&at,   g_at);

  cudaFuncSetAttribute(gemm_fp16<float>,  cudaFuncAttributeMaxDynamicSharedMemorySize, SMEM_SZ);
  cudaFuncSetAttribute(gemm_fp16<__half>, cudaFuncAttributeMaxDynamicSharedMemorySize, SMEM_SZ);

  // 0) convert / transpose inputs to fp16
  conv_half<<<((size_t)NB*NS*ND)/1024, 256>>>(hid, hidh);
  transpose_w<<<dim3((3*ND)/32, ND/32), dim3(32,8)>>>(wqkv, wqkvT, ND, 3*ND);
  transpose_w<<<dim3(ND/32, ND/32),     dim3(32,8)>>>(wout, woutT, ND, ND);

  // 1) qkv = hid @ WqkvT^T   (fp16 out)
  gemm_fp16<__half><<<dim3((3*ND)/128,(NB*NS)/128,1),256,SMEM_SZ>>>(
      hidh,wqkvT,qkv, ND, ND,ND,3*ND, 0,0, 0,0,1, 0);

  // 2) split + rope
  prep_rope<<<(3*NB*NH*NS*64)/256,256>>>(qkv,pos,q,k,v);
  transpose_v<<<dim3(NHD/32,NS/32,NB*NH), dim3(32,8)>>>(v, vT);

  // 3) scores = Q @ K^T (fp32 out, causal block-skip)
  gemm_fp16<float><<<dim3(NS/128,NS/128,NB*NH),256,SMEM_SZ>>>(
      q,k,sc, NHD, NHD,NHD,NS,
      (long long)NS*NHD,(long long)NS*NHD,
      (long long)NS*NS,0,1, 1);

  // 4) softmax: fp32 scores -> fp16 probs
  softmax_causal<<<dim3(NS,NB*NH),256>>>(sc, pr);

  // 5) attn = P @ V (causal K-limit), fp16 out in [B,S,D]
  gemm_fp16<__half><<<dim3(NHD/128,NS/128,NB*NH),256,SMEM_SZ>>>(
      pr,vT,at, NS, NS,NS,ND,
      (long long)NS*NS,(long long)NHD*NS,
      (long long)NS*ND,(long long)NHD,NH, 2);

  // 6) out = attn @ WoutT^T (fp32 out)
  gemm_fp16<float><<<dim3(ND/128,(NB*NS)/128,1),256,SMEM_SZ>>>(
      at,woutT,out, ND, ND,ND,ND, 0,0, 0,0,1, 0);
}

// round 12
// speedup vs baseline: 3.1435x; 1.0532x over previous
#include <cuda_runtime.h>
#include <cuda_fp16.h>
#include <cstdint>

#define NB 2
#define NS 2048
#define ND 4096
#define NH 16
#define NHD 256

#define BK 64                    // K halfs per tile = 128B SW128 row
#define STAGE_M 16384            // one 128-row x 128B matrix
#define STAGE_SZ (2*STAGE_M)     // A + B = 32KB
#define NSTAGE 3
#define SMEM_SZ (NSTAGE*STAGE_SZ)   // 98304 -> 2 CTAs/SM

// ---------------- scratch (__device__ globals; no allocation) ----------------
static __device__ __half g_hid  [(size_t)NB*NS*ND];     // fp16 hidden
static __device__ __half g_wqkvT[(size_t)3*ND*ND];      // [3D, D] fp16
static __device__ __half g_woutT[(size_t)ND*ND];        // [D, D] fp16
static __device__ __half g_q    [(size_t)NB*NH*NS*NHD]; // [B,H,S,hd] fp16 (roped)
static __device__ __half g_k    [(size_t)NB*NH*NS*NHD]; // [B,H,S,hd] fp16 (roped)
static __device__ __half g_vT   [(size_t)NB*NH*NHD*NS]; // [B,H,hd,S] fp16
static __device__ float  g_sc   [(size_t)NB*NH*NS*NS];  // scores fp32
static __device__ __half g_p    [(size_t)NB*NH*NS*NS];  // probs fp16
static __device__ __half g_at   [(size_t)NB*NS*ND];     // [B,S,D] fp16

// ---------------- helpers ----------------
__device__ __forceinline__ void mmaop(float* c, const unsigned* a, const unsigned* b){
  asm volatile(
    "mma.sync.aligned.m16n8k16.row.col.f32.f16.f16.f32 "
    "{%0,%1,%2,%3},{%4,%5,%6,%7},{%8,%9},{%0,%1,%2,%3};\n"
    : "+f"(c[0]),"+f"(c[1]),"+f"(c[2]),"+f"(c[3])
    : "r"(a[0]),"r"(a[1]),"r"(a[2]),"r"(a[3]),"r"(b[0]),"r"(b[1]));
}
__device__ __forceinline__ void ldsm4(unsigned addr, unsigned* r){
  asm volatile("ldmatrix.sync.aligned.m8n8.x4.shared.b16 {%0,%1,%2,%3}, [%4];"
    : "=r"(r[0]),"=r"(r[1]),"=r"(r[2]),"=r"(r[3]) : "r"(addr));
}
__device__ __forceinline__ void cpa16(unsigned dst, const void* g){
  asm volatile("cp.async.cg.shared.global [%0],[%1],16;\n"::"r"(dst),"l"(g));
}
#define CP_COMMIT() asm volatile("cp.async.commit_group;\n")
#define CP_WAIT1()  asm volatile("cp.async.wait_group 1;\n")
__device__ __forceinline__ unsigned smem_u32(const void* p){
  unsigned a; asm("{ .reg .u64 t; cvta.to.shared.u64 t, %1; cvt.u32.u64 %0, t; }":"=r"(a):"l"(p));
  return a;
}
__device__ __forceinline__ void st2(float* p, float x, float y){
  *(float2*)p = make_float2(x,y);
}
__device__ __forceinline__ void st2(__half* p, float x, float y){
  *(__half2*)p = __floats2half2_rn(x,y);
}

// ============================================================================
// fp16 GEMM via mma.sync(m16n8k16) + ldmatrix: C = A[M,K] * B[N,K]^T, K-major
// fp16 in, fp32 accumulate. CTA 128x128 (8 warps, 64x32 warp tile), BK=64,
// SW128 swizzle, 3-stage cp.async, one __syncthreads per tile.
// causal==1: skip bn>bm.  causal==2: kend=(bm+1)*128.
// epi==1: QKV rope-split epilogue -> writes qo/ko (roped, [B,H,S,hd]) and
//         vo (transposed, [B,H,hd,S]); C unused.
// else:   C offset = (z/cdiv)*cs1 + (z%cdiv)*cs2.
// ============================================================================
template<typename CT>
__global__ void __launch_bounds__(256,2) gemm_fp16(
  const __half* __restrict__ A, const __half* __restrict__ B, CT* __restrict__ C,
  int K,int lda,int ldb,int ldc,
  long long sA,long long sB,long long cs1,long long cs2,int cdiv,
  int causal,int epi,
  const int* __restrict__ pos, __half* __restrict__ qo,
  __half* __restrict__ ko, __half* __restrict__ vo)
{
  const int bn=blockIdx.x, bm=blockIdx.y, z=blockIdx.z;
  if(causal==1 && bn>bm) return;
  int kend=K;
  if(causal==2){ int ke=(bm+1)*128; if(ke<kend) kend=ke; }
  const int nk = kend>>6;            // >= 2 for every launch here

  extern __shared__ float smem[];
  const unsigned sb = smem_u32(smem);

  const int tid=threadIdx.x, warp=tid>>5, lane=tid&31;
  const int wm=warp>>2, wn=warp&3;           // 2x4 warp grid; warp tile 64x32
  const int gq=lane>>2, tg=lane&3;

  const __half* Ab = A + (long long)z*sA + (long long)(bm*128)*lda;
  const __half* Bb = B + (long long)z*sB + (long long)(bn*128)*ldb;

  // staging: 1024 16B-chunks per matrix; thread t covers chunks {t,+256,+512,+768}
  const __half* gA[4]; const __half* gB[4]; unsigned sAo[4];
#pragma unroll
  for(int i=0;i<4;i++){
    int q=i*256+tid, row=q>>3, c=q&7;
    sAo[i] = (unsigned)(row*128 + ((c ^ (row&7))<<4));   // SW128
    gA[i]=Ab + (long long)row*lda + c*8;
    gB[i]=Bb + (long long)row*ldb + c*8;
  }

  auto stage=[&](int kt,int s){
    unsigned base = sb + s*STAGE_SZ;
#pragma unroll
    for(int i=0;i<4;i++) cpa16(base + sAo[i],           gA[i] + kt*BK);
#pragma unroll
    for(int i=0;i<4;i++) cpa16(base + STAGE_M + sAo[i], gB[i] + kt*BK);
  };

  // ldmatrix per-lane row constants
  const int lrow = lane & 15;
  const unsigned klane = lane >> 4;
  unsigned ar128[4], ar7[4], br128[2], br7[2];
#pragma unroll
  for(int mi=0;mi<4;mi++){
    int r = wm*64 + mi*16 + lrow;
    ar128[mi] = r*128; ar7[mi] = r&7;
  }
#pragma unroll
  for(int p=0;p<2;p++){
    int r = wn*32 + p*16 + lrow;
    br128[p] = r*128 + STAGE_M; br7[p] = r&7;
  }

  float acc[4][4][4];
#pragma unroll
  for(int i=0;i<4;i++)
#pragma unroll
    for(int j=0;j<4;j++)
#pragma unroll
      for(int l=0;l<4;l++) acc[i][j][l]=0.f;

  stage(0,0); CP_COMMIT();
  stage(1,1); CP_COMMIT();

  for(int kt=0; kt<nk; ++kt){
    CP_WAIT1();
    __syncthreads();

    if(kt+2<nk) stage(kt+2,(kt+2)%3);
    CP_COMMIT();

    const unsigned base = sb + (unsigned)(kt%3)*STAGE_SZ;
#pragma unroll
    for(int ks=0;ks<4;ks++){
      const unsigned ck = ks*2 + klane;
      unsigned a[4][4], br[2][4];
#pragma unroll
      for(int mi=0;mi<4;mi++)
        ldsm4(base + ar128[mi] + (((ck ^ ar7[mi]))<<4), a[mi]);
#pragma unroll
      for(int p=0;p<2;p++)
        ldsm4(base + br128[p] + (((ck ^ br7[p]))<<4), br[p]);
      unsigned b[4][2];
#pragma unroll
      for(int p=0;p<2;p++){
        b[2*p  ][0]=br[p][0]; b[2*p  ][1]=br[p][2];
        b[2*p+1][0]=br[p][1]; b[2*p+1][1]=br[p][3];
      }
#pragma unroll
      for(int mi=0;mi<4;mi++)
#pragma unroll
        for(int ni=0;ni<4;ni++)
          mmaop(acc[mi][ni], a[mi], b[ni]);
    }
  }

  if(epi){
    // ---- fused rope/split epilogue (QKV GEMM) ----
    // column block is uniform in (tensor, head): 128 | 256 | 4096 alignments
    const int cbase = bn*128;
    const int tensor = cbase >> 12;          // 0:q 1:k 2:v
    const int h = (cbase >> 8) & (NH-1);
#pragma unroll
    for(int mi=0;mi<4;mi++){
      int r0 = bm*128 + wm*64 + mi*16 + gq;  // global row; r0+8 same b
      int b0 = r0 >> 11, s0 = r0 & (NS-1);   // s0+8 no wrap (r0 mod 16 < 8)
      int p0 = pos[b0*NS+s0], p1 = pos[b0*NS+s0+8];
      const long long zz = (long long)(b0*NH + h);
#pragma unroll
      for(int ni=0;ni<4;ni++){
        int c0 = cbase + wn*32 + ni*8 + tg*2;   // even: rope pair (c0,c0+1)
        int hcol = c0 & (NHD-1);
        float x0=acc[mi][ni][0], y0=acc[mi][ni][1];   // row s0
        float x1=acc[mi][ni][2], y1=acc[mi][ni][3];   // row s0+8
        if(tensor<2 && hcol<64){
          float inv = powf(10000.f, -(float)hcol*(1.0f/64.0f));
          float f0 = (float)p0*inv, f1 = (float)p1*inv;
          float c_0=cosf(f0), s_0=sinf(f0), c_1=cosf(f1), s_1=sinf(f1);
          float nx0 = x0*c_0 - y0*s_0, ny0 = y0*c_0 + x0*s_0;
          float nx1 = x1*c_1 - y1*s_1, ny1 = y1*c_1 + x1*s_1;
          x0=nx0; y0=ny0; x1=nx1; y1=ny1;
        }
        if(tensor==2){
          // vT[(zz*NHD + hcol)*NS + s]
          __half* vp = vo + (zz*NHD + hcol)*NS;
          vp[s0]        = __float2half_rn(x0);
          vp[s0+8]      = __float2half_rn(x1);
          vp += NS;     // hcol+1
          vp[s0]        = __float2half_rn(y0);
          vp[s0+8]      = __float2half_rn(y1);
        }else{
          __half* dst = (tensor? ko : qo) + (zz*NS + s0)*NHD + hcol;
          *(__half2*)dst            = __floats2half2_rn(x0,y0);
          *(__half2*)(dst + 8*NHD)  = __floats2half2_rn(x1,y1);
        }
      }
    }
    return;
  }

  const long long coff = (long long)(z/cdiv)*cs1 + (long long)(z%cdiv)*cs2;
#pragma unroll
  for(int mi=0;mi<4;mi++){
    int r0 = bm*128 + wm*64 + mi*16 + gq;
#pragma unroll
    for(int ni=0;ni<4;ni++){
      int c0 = bn*128 + wn*32 + ni*8 + tg*2;
      CT* p = C + coff + (long long)r0*ldc + c0;
      st2(p,             acc[mi][ni][0], acc[mi][ni][1]);
      st2(p + 8LL*ldc,   acc[mi][ni][2], acc[mi][ni][3]);
    }
  }
}

// ---------------- fp32 -> fp16 copy ----------------
__global__ __launch_bounds__(256) void conv_half(const float* __restrict__ in, __half* __restrict__ out){
  size_t i = (size_t)(blockIdx.x*256u + threadIdx.x)*4u;
  float4 v = *(const float4*)(in+i);
  *(__half2*)(out+i)   = __floats2half2_rn(v.x,v.y);
  *(__half2*)(out+i+2) = __floats2half2_rn(v.z,v.w);
}

// ---------------- weight transpose [K,N] fp32 -> [N,K] fp16 ----------------
__global__ __launch_bounds__(256) void transpose_w(const float* __restrict__ in, __half* __restrict__ out,
                                                   int K,int N){
  __shared__ float t[32][33];
  int n0=blockIdx.x*32, k0=blockIdx.y*32;
  int tx=threadIdx.x, ty=threadIdx.y;        // 32 x 8
#pragma unroll
  for(int j=0;j<4;j++) t[ty+8*j][tx] = in[(long long)(k0+ty+8*j)*N + n0+tx];
  __syncthreads();
#pragma unroll
  for(int j=0;j<4;j++) out[(long long)(n0+ty+8*j)*K + k0+tx] = __float2half_rn(t[tx][ty+8*j]);
}

// -------- causal softmax: fp32 scores -> fp16 probs (zero-fill to 128 bdry) --
__global__ __launch_bounds__(256) void softmax_causal(const float* __restrict__ sc,
                                                      __half* __restrict__ pr){
  const int m=blockIdx.x, z=blockIdx.y;
  const float* row = sc + ((long long)z*NS + m)*NS;
  __half* rowp     = pr + ((long long)z*NS + m)*NS;
  const int valid=m+1;
  const int zlim=((m>>7)+1)<<7;
  const int tid=threadIdx.x;
  const float scale=0.0625f;
  float vals[8];
  float mx=-3.0e38f;
#pragma unroll
  for(int i=0;i<8;i++){
    int j=tid+(i<<8);
    float vv=-3.0e38f;
    if(j<valid) vv=row[j]*scale;
    vals[i]=vv; mx=fmaxf(mx,vv);
  }
  __shared__ float redm[8], reds[8];
#pragma unroll
  for(int o=16;o>0;o>>=1) mx=fmaxf(mx,__shfl_xor_sync(0xffffffffu,mx,o));
  if((tid&31)==0) redm[tid>>5]=mx;
  __syncthreads();
  mx=redm[0];
#pragma unroll
  for(int i=1;i<8;i++) mx=fmaxf(mx,redm[i]);
  float sum=0.f;
#pragma unroll
  for(int i=0;i<8;i++){ float e=expf(vals[i]-mx); vals[i]=e; sum+=e; }
#pragma unroll
  for(int o=16;o>0;o>>=1) sum+=__shfl_xor_sync(0xffffffffu,sum,o);
  if((tid&31)==0) reds[tid>>5]=sum;
  __syncthreads();
  sum=0.f;
#pragma unroll
  for(int i=0;i<8;i++) sum+=reds[i];
  float inv=1.0f/sum;
#pragma unroll
  for(int i=0;i<8;i++){
    int j=tid+(i<<8);
    if(j<zlim) rowp[j] = __float2half_rn((j<valid)? vals[i]*inv : 0.f);
  }
}

// ---------------- launch ----------------
extern "C" void kernel_launch(void* const* d_in, const int* in_sizes, int n_in,
                              void* d_out, int out_size)
{
  const int*   pos  = (const int*)d_in[0];
  const float* hid  = (const float*)d_in[1];
  const float* wqkv = (const float*)d_in[2];
  const float* wout = (const float*)d_in[3];
  float* out = (float*)d_out;

  __half *hidh,*wqkvT,*woutT,*q,*k,*vT,*pr,*at;
  float *sc;
  cudaGetSymbolAddress((void**)&hidh, g_hid);
  cudaGetSymbolAddress((void**)&wqkvT,g_wqkvT);
  cudaGetSymbolAddress((void**)&woutT,g_woutT);
  cudaGetSymbolAddress((void**)&q,    g_q);
  cudaGetSymbolAddress((void**)&k,    g_k);
  cudaGetSymbolAddress((void**)&vT,   g_vT);
  cudaGetSymbolAddress((void**)&sc,   g_sc);
  cudaGetSymbolAddress((void**)&pr,   g_p);
  cudaGetSymbolAddress((void**)&at,   g_at);

  cudaFuncSetAttribute(gemm_fp16<float>,  cudaFuncAttributeMaxDynamicSharedMemorySize, SMEM_SZ);
  cudaFuncSetAttribute(gemm_fp16<__half>, cudaFuncAttributeMaxDynamicSharedMemorySize, SMEM_SZ);

  // 0) convert / transpose inputs to fp16
  conv_half<<<((size_t)NB*NS*ND)/1024, 256>>>(hid, hidh);
  transpose_w<<<dim3((3*ND)/32, ND/32), dim3(32,8)>>>(wqkv, wqkvT, ND, 3*ND);
  transpose_w<<<dim3(ND/32, ND/32),     dim3(32,8)>>>(wout, woutT, ND, ND);

  // 1) QKV GEMM with fused rope/split epilogue -> q, k (roped), vT (transposed)
  gemm_fp16<__half><<<dim3((3*ND)/128,(NB*NS)/128,1),256,SMEM_SZ>>>(
      hidh,wqkvT,at /*unused*/, ND, ND,ND,0, 0,0, 0,0,1, 0,1, pos,q,k,vT);

  // 2) scores = Q @ K^T (fp32 out, causal block-skip)
  gemm_fp16<float><<<dim3(NS/128,NS/128,NB*NH),256,SMEM_SZ>>>(
      q,k,sc, NHD, NHD,NHD,NS,
      (long long)NS*NHD,(long long)NS*NHD,
      (long long)NS*NS,0,1, 1,0, pos,0,0,0);

  // 3) softmax: fp32 scores -> fp16 probs
  softmax_causal<<<dim3(NS,NB*NH),256>>>(sc, pr);

  // 4) attn = P @ V (causal K-limit), fp16 out in [B,S,D]
  gemm_fp16<__half><<<dim3(NHD/128,NS/128,NB*NH),256,SMEM_SZ>>>(
      pr,vT,at, NS, NS,NS,ND,
      (long long)NS*NS,(long long)NHD*NS,
      (long long)NS*ND,(long long)NHD,NH, 2,0, pos,0,0,0);

  // 5) out = attn @ WoutT^T (fp32 out)
  gemm_fp16<float><<<dim3(ND/128,(NB*NS)/128,1),256,SMEM_SZ>>>(
      at,woutT,out, ND, ND,ND,ND, 0,0, 0,0,1, 0,0, pos,0,0,0);
}